// round 14
// baseline (speedup 1.0000x reference)
#include <cuda_runtime.h>
#include <cuda_bf16.h>
#include <cstdint>

#define BATCH 256
#define SEQ   128
#define D_IN  1024
#define D_HID 2048
#define N_CLS 1024

typedef __nv_bfloat16 bf;

// ---------------- scratch (__device__ globals; no cudaMalloc allowed) -------
__device__ float g_xproj[(size_t)BATCH * SEQ * D_HID];            // 268 MB
__device__ bf    g_xp_hi[(size_t)BATCH * SEQ * D_HID];            // 134 MB
__device__ bf    g_xp_lo[(size_t)BATCH * SEQ * D_HID];
__device__ bf    g_x_hi [(size_t)BATCH * SEQ * D_IN];
__device__ bf    g_x_lo [(size_t)BATCH * SEQ * D_IN];
__device__ bf    g_Whx_hi[(size_t)D_HID * D_IN];
__device__ bf    g_Whx_lo[(size_t)D_HID * D_IN];
__device__ bf    g_Wph_hi[(size_t)N_CLS * D_HID];
__device__ bf    g_Wph_lo[(size_t)N_CLS * D_HID];
__device__ bf    g_whh_hi [(size_t)D_HID * D_HID];
__device__ bf    g_whh_lo [(size_t)D_HID * D_HID];
__device__ bf    g_whh_hiT[(size_t)D_HID * D_HID];
__device__ bf    g_whh_loT[(size_t)D_HID * D_HID];
__device__ bf    g_pw_hi [2][(size_t)D_HID * D_HID];
__device__ bf    g_pw_lo [2][(size_t)D_HID * D_HID];
__device__ bf    g_pw_hiT[2][(size_t)D_HID * D_HID];
__device__ bf    g_pw_loT[2][(size_t)D_HID * D_HID];
__device__ float g_pw_f32[(size_t)D_HID * D_HID];
__device__ float g_dA_f[(size_t)64 * BATCH * D_HID];
__device__ bf    g_dA_h[(size_t)64 * BATCH * D_HID];
__device__ bf    g_dA_l[(size_t)64 * BATCH * D_HID];
__device__ float g_dB_f[(size_t)64 * BATCH * D_HID];
__device__ bf    g_dB_h[(size_t)64 * BATCH * D_HID];
__device__ bf    g_dB_l[(size_t)64 * BATCH * D_HID];

// ---------------- portable PTX helpers (compute_103 baseline, no 'a') -------
__device__ __forceinline__ uint32_t smem_to_u32(const void* p) {
    uint32_t a;
    asm("{ .reg .u64 t; cvta.to.shared.u64 t, %1; cvt.u32.u64 %0, t; }" : "=r"(a) : "l"(p));
    return a;
}
#define CP_ASYNC16(dst, src) \
    asm volatile("cp.async.cg.shared.global [%0], [%1], 16;" :: "r"(dst), "l"(src) : "memory")
#define CP_COMMIT() asm volatile("cp.async.commit_group;" ::: "memory")
#define CP_WAIT0()  asm volatile("cp.async.wait_group 0;" ::: "memory")
#define CP_WAIT1()  asm volatile("cp.async.wait_group 1;" ::: "memory")

__device__ __forceinline__ void ldsm_x4(uint32_t* r, uint32_t addr) {
    asm volatile("ldmatrix.sync.aligned.m8n8.x4.shared.b16 {%0,%1,%2,%3}, [%4];"
                 : "=r"(r[0]), "=r"(r[1]), "=r"(r[2]), "=r"(r[3]) : "r"(addr));
}
__device__ __forceinline__ void mma_bf16(float* c, const uint32_t* a, const uint32_t* b) {
    asm volatile("mma.sync.aligned.m16n8k16.row.col.f32.bf16.bf16.f32 "
                 "{%0,%1,%2,%3}, {%4,%5,%6,%7}, {%8,%9}, {%0,%1,%2,%3};"
                 : "+f"(c[0]), "+f"(c[1]), "+f"(c[2]), "+f"(c[3])
                 : "r"(a[0]), "r"(a[1]), "r"(a[2]), "r"(a[3]), "r"(b[0]), "r"(b[1]));
}
__device__ __forceinline__ uint32_t swz(uint32_t off) {
    return off ^ ((off >> 3) & 0x70);
}
__device__ __forceinline__ void split1(float v, bf& h, bf& l) {
    h = __float2bfloat16(v);
    l = __float2bfloat16(v - __bfloat162float(h));
}

// ---------------------------------------------------------------------------
// HMMA split-bf16 GEMM (fused 3 products: Ahi.Bhi + Ahi.Blo + Alo.Bhi).
// A addressing supports 256-row "paired block" layouts:
//   row m -> A + (m/256)*bsA + (m%256)*ldA   (plain GEMM: bsA = 256*ldA)
// PARITY mode (scan combines): sequence = 256 rows; seq index = (bm*BM)>>8.
//   even seq -> write hi/lo only (next level's A); odd -> fp32 only (next Add).
// ---------------------------------------------------------------------------
template <int BM, int BN, int WM, int WN, bool ADD, bool BIAS, bool OUT_F32,
          bool OUT_SPLIT, bool PARITY>
__global__ __launch_bounds__((BM / WM) * (BN / WN) * 32) void rnn_gemm(
    int M, int N, int K,
    const bf* __restrict__ Ahi, const bf* __restrict__ Alo, size_t ldA, size_t bsA,
    const bf* __restrict__ Bhi, const bf* __restrict__ Blo,
    const float* __restrict__ Add, size_t ldAdd, size_t bsAdd,
    const float* __restrict__ bias,
    float* __restrict__ C, bf* __restrict__ Chi, bf* __restrict__ Clo)
{
    constexpr int THREADS = (BM / WM) * (BN / WN) * 32;
    constexpr int ATILE = BM * 128;
    constexpr int BTILE = BN * 128;
    constexpr int BUF = 2 * ATILE + 2 * BTILE;
    constexpr int MI = WM / 16, NI = WN / 8, NJ = WN / 16;

    extern __shared__ __align__(1024) char smem[];
    const uint32_t sbase = smem_to_u32(smem);

    const int tid  = threadIdx.x;
    const int lane = tid & 31;
    const int wid  = tid >> 5;
    constexpr int WARPS_N = BN / WN;
    const int warp_n = wid % WARPS_N;
    const int warp_m = wid / WARPS_N;
    const int bn = blockIdx.x;
    const int bm = blockIdx.y;

    const size_t blk   = (size_t)((unsigned)(bm * BM) >> 8);
    const int    rowin = (bm * BM) & 255;
    const bf* AhE = Ahi + blk * bsA + (size_t)rowin * ldA;
    const bf* AlE = Alo + blk * bsA + (size_t)rowin * ldA;
    const float* AddE = nullptr;
    if (ADD) AddE = Add + blk * bsAdd + (size_t)rowin * ldAdd;
    const int par = PARITY ? ((int)blk & 1) : 0;

    const int NIT = K >> 6;

    auto issueTiles = [&](int it, int buf) {
        const int kb = it << 6;
        const char* AgH = (const char*)(AhE + kb);
        const char* AgL = (const char*)(AlE + kb);
        const char* BgH = (const char*)(Bhi + (size_t)(bn * BN) * K + kb);
        const char* BgL = (const char*)(Blo + (size_t)(bn * BN) * K + kb);
        const uint32_t s0 = sbase + buf * BUF;
        const size_t rsA = ldA * 2;
        const size_t rsB = (size_t)K * 2;
#pragma unroll
        for (int j = 0; j < BM * 8 / THREADS; j++) {
            int c = tid + j * THREADS;
            int r = c >> 3, col = (c & 7) << 4;
            uint32_t off = swz((uint32_t)(r * 128 + col));
            size_t g = (size_t)r * rsA + col;
            CP_ASYNC16(s0 + off, AgH + g);
            CP_ASYNC16(s0 + ATILE + off, AgL + g);
        }
#pragma unroll
        for (int j = 0; j < BN * 8 / THREADS; j++) {
            int c = tid + j * THREADS;
            int r = c >> 3, col = (c & 7) << 4;
            uint32_t off = swz((uint32_t)(r * 128 + col));
            size_t g = (size_t)r * rsB + col;
            CP_ASYNC16(s0 + 2 * ATILE + off, BgH + g);
            CP_ASYNC16(s0 + 2 * ATILE + BTILE + off, BgL + g);
        }
    };

    float acc[MI][NI][4];
#pragma unroll
    for (int i = 0; i < MI; i++)
#pragma unroll
        for (int j = 0; j < NI; j++)
#pragma unroll
            for (int e = 0; e < 4; e++) acc[i][j][e] = 0.0f;

    issueTiles(0, 0);
    CP_COMMIT();

    for (int it = 0; it < NIT; it++) {
        const int buf = it & 1;
        if (it + 1 < NIT) {
            issueTiles(it + 1, buf ^ 1);
            CP_COMMIT();
            CP_WAIT1();
        } else {
            CP_WAIT0();
        }
        __syncthreads();

        const uint32_t sAh = sbase + buf * BUF;
        const uint32_t sAl = sAh + ATILE;
        const uint32_t sBh = sAh + 2 * ATILE;
        const uint32_t sBl = sBh + BTILE;
#pragma unroll
        for (int s = 0; s < 4; s++) {
            const int k0 = s * 16;
            uint32_t ah[MI][4], al[MI][4], bh[NJ][4], bl[NJ][4];
#pragma unroll
            for (int i = 0; i < MI; i++) {
                int row = warp_m * WM + i * 16 + (lane & 15);
                int kc  = k0 + (lane >> 4) * 8;
                uint32_t off = swz((uint32_t)(row * 128 + kc * 2));
                ldsm_x4(ah[i], sAh + off);
                ldsm_x4(al[i], sAl + off);
            }
#pragma unroll
            for (int j = 0; j < NJ; j++) {
                int n  = warp_n * WN + j * 16 + (lane & 7) + ((lane >> 4) & 1) * 8;
                int kc = k0 + ((lane >> 3) & 1) * 8;
                uint32_t off = swz((uint32_t)(n * 128 + kc * 2));
                ldsm_x4(bh[j], sBh + off);
                ldsm_x4(bl[j], sBl + off);
            }
#pragma unroll
            for (int i = 0; i < MI; i++)
#pragma unroll
                for (int j = 0; j < NI; j++) {
                    mma_bf16(acc[i][j], ah[i], &bh[j >> 1][(j & 1) * 2]);
                    mma_bf16(acc[i][j], ah[i], &bl[j >> 1][(j & 1) * 2]);
                    mma_bf16(acc[i][j], al[i], &bh[j >> 1][(j & 1) * 2]);
                }
        }
        __syncthreads();
    }

    // ---- epilogue ----
    const int tg = lane >> 2, tr = lane & 3;
#pragma unroll
    for (int i = 0; i < MI; i++) {
#pragma unroll
        for (int j = 0; j < NI; j++) {
            const int col = bn * BN + warp_n * WN + j * 8 + tr * 2;
            const int lr0 = warp_m * WM + i * 16 + tg;
            const int lr1 = lr0 + 8;
            const int row0 = bm * BM + lr0;
            const int row1 = bm * BM + lr1;
            float2 v0 = make_float2(acc[i][j][0], acc[i][j][1]);
            float2 v1 = make_float2(acc[i][j][2], acc[i][j][3]);
            if (ADD) {
                float2 a0 = *(const float2*)&AddE[(size_t)lr0 * ldAdd + col];
                float2 a1 = *(const float2*)&AddE[(size_t)lr1 * ldAdd + col];
                v0.x += a0.x; v0.y += a0.y; v1.x += a1.x; v1.y += a1.y;
            }
            if (BIAS) {
                float2 bb = *(const float2*)&bias[col];
                v0.x += bb.x; v0.y += bb.y; v1.x += bb.x; v1.y += bb.y;
            }
            if (OUT_F32 && (!PARITY || par == 1)) {
                *(float2*)&C[(size_t)row0 * N + col] = v0;
                *(float2*)&C[(size_t)row1 * N + col] = v1;
            }
            if (OUT_SPLIT && (!PARITY || par == 0)) {
                bf h0, h1, h2, h3, l0, l1, l2, l3;
                split1(v0.x, h0, l0); split1(v0.y, h1, l1);
                split1(v1.x, h2, l2); split1(v1.y, h3, l3);
                __nv_bfloat162 hp0{h0, h1}, hp1{h2, h3}, lp0{l0, l1}, lp1{l2, l3};
                *(uint32_t*)&Chi[(size_t)row0 * N + col] = *(uint32_t*)&hp0;
                *(uint32_t*)&Chi[(size_t)row1 * N + col] = *(uint32_t*)&hp1;
                *(uint32_t*)&Clo[(size_t)row0 * N + col] = *(uint32_t*)&lp0;
                *(uint32_t*)&Clo[(size_t)row1 * N + col] = *(uint32_t*)&lp1;
            }
        }
    }
}

// ---------------- fp32 -> bf16 hi/lo split (plain) ---------------------------
__global__ void split_kernel(const float* __restrict__ src,
                             bf* __restrict__ hi, bf* __restrict__ lo, size_t n4)
{
    size_t i = (size_t)blockIdx.x * blockDim.x + threadIdx.x;
    if (i >= n4) return;
    float4 v = ((const float4*)src)[i];
    bf h0, h1, h2, h3, l0, l1, l2, l3;
    split1(v.x, h0, l0); split1(v.y, h1, l1); split1(v.z, h2, l2); split1(v.w, h3, l3);
    __nv_bfloat162 hp0{h0, h1}, hp1{h2, h3}, lp0{l0, l1}, lp1{l2, l3};
    uint2 hw, lw;
    hw.x = *(uint32_t*)&hp0; hw.y = *(uint32_t*)&hp1;
    lw.x = *(uint32_t*)&lp0; lw.y = *(uint32_t*)&lp1;
    ((uint2*)hi)[i] = hw;
    ((uint2*)lo)[i] = lw;
}

// ---------------- fp32 2048x2048 -> split (normal) + split (transposed) ------
__global__ void transpose_split(const float* __restrict__ V,
                                bf* __restrict__ hi, bf* __restrict__ lo,
                                bf* __restrict__ hiT, bf* __restrict__ loT)
{
    __shared__ float t[32][33];
    const int bx = blockIdx.x * 32;
    const int by = blockIdx.y * 32;
    const int tx = threadIdx.x, ty = threadIdx.y;
#pragma unroll
    for (int j = 0; j < 4; j++) {
        int r = by + ty + j * 8;
        float v = V[(size_t)r * D_HID + bx + tx];
        t[ty + j * 8][tx] = v;
        bf h, l; split1(v, h, l);
        hi[(size_t)r * D_HID + bx + tx] = h;
        lo[(size_t)r * D_HID + bx + tx] = l;
    }
    __syncthreads();
#pragma unroll
    for (int j = 0; j < 4; j++) {
        int ct = ty + j * 8;
        float v = t[tx][ct];
        bf h, l; split1(v, h, l);
        hiT[(size_t)(bx + ct) * D_HID + by + tx] = h;
        loT[(size_t)(bx + ct) * D_HID + by + tx] = l;
    }
}

// ---------------------------------------------------------------------------
extern "C" void kernel_launch(void* const* d_in, const int* in_sizes, int n_in,
                              void* d_out, int out_size)
{
    const float* x    = (const float*)d_in[0];
    const float* W_hx = (const float*)d_in[1];
    const float* W_hh = (const float*)d_in[2];
    const float* W_ph = (const float*)d_in[3];
    const float* b_h  = (const float*)d_in[4];
    const float* b_p  = (const float*)d_in[5];
    float* out = (float*)d_out;

    float *xproj, *pw_f32, *dA_f, *dB_f;
    bf *xp_hi, *xp_lo, *x_hi, *x_lo, *whx_hi, *whx_lo, *wph_hi, *wph_lo;
    bf *whh_hi, *whh_lo, *whh_hiT, *whh_loT;
    bf *pw_hi, *pw_lo, *pw_hiT, *pw_loT;
    bf *dA_h, *dA_l, *dB_h, *dB_l;
    cudaGetSymbolAddress((void**)&xproj,   g_xproj);
    cudaGetSymbolAddress((void**)&xp_hi,   g_xp_hi);
    cudaGetSymbolAddress((void**)&xp_lo,   g_xp_lo);
    cudaGetSymbolAddress((void**)&x_hi,    g_x_hi);
    cudaGetSymbolAddress((void**)&x_lo,    g_x_lo);
    cudaGetSymbolAddress((void**)&whx_hi,  g_Whx_hi);
    cudaGetSymbolAddress((void**)&whx_lo,  g_Whx_lo);
    cudaGetSymbolAddress((void**)&wph_hi,  g_Wph_hi);
    cudaGetSymbolAddress((void**)&wph_lo,  g_Wph_lo);
    cudaGetSymbolAddress((void**)&whh_hi,  g_whh_hi);
    cudaGetSymbolAddress((void**)&whh_lo,  g_whh_lo);
    cudaGetSymbolAddress((void**)&whh_hiT, g_whh_hiT);
    cudaGetSymbolAddress((void**)&whh_loT, g_whh_loT);
    cudaGetSymbolAddress((void**)&pw_hi,   g_pw_hi);
    cudaGetSymbolAddress((void**)&pw_lo,   g_pw_lo);
    cudaGetSymbolAddress((void**)&pw_hiT,  g_pw_hiT);
    cudaGetSymbolAddress((void**)&pw_loT,  g_pw_loT);
    cudaGetSymbolAddress((void**)&pw_f32,  g_pw_f32);
    cudaGetSymbolAddress((void**)&dA_f,    g_dA_f);
    cudaGetSymbolAddress((void**)&dA_h,    g_dA_h);
    cudaGetSymbolAddress((void**)&dA_l,    g_dA_l);
    cudaGetSymbolAddress((void**)&dB_f,    g_dB_f);
    cudaGetSymbolAddress((void**)&dB_h,    g_dB_h);
    cudaGetSymbolAddress((void**)&dB_l,    g_dB_l);
    const size_t PW = (size_t)D_HID * D_HID;

    // big 256x128 tile kernels (512 threads), small 64x64 for readout
    auto kXproj  = rnn_gemm<256, 128, 64, 32, false, true,  true,  true,  false>;
    auto kComb   = rnn_gemm<256, 128, 64, 32, true,  false, true,  true,  true>;
    auto kSquare = rnn_gemm<256, 128, 64, 32, false, false, true,  false, false>;
    auto kOut    = rnn_gemm<64,  64,  32, 32, false, true,  true,  false, false>;
    const int SMEM_BIG = 2 * (2 * 256 * 128 + 2 * 128 * 128);   // 196608
    const int SMEM_SM  = 2 * (2 * 64 * 128 + 2 * 64 * 128);     // 65536
    cudaFuncSetAttribute(kXproj,  cudaFuncAttributeMaxDynamicSharedMemorySize, SMEM_BIG);
    cudaFuncSetAttribute(kComb,   cudaFuncAttributeMaxDynamicSharedMemorySize, SMEM_BIG);
    cudaFuncSetAttribute(kSquare, cudaFuncAttributeMaxDynamicSharedMemorySize, SMEM_BIG);
    cudaFuncSetAttribute(kOut,    cudaFuncAttributeMaxDynamicSharedMemorySize, SMEM_SM);

    // 0) input/weight splits
    {
        size_t n4;
        n4 = (size_t)BATCH * SEQ * D_IN / 4;
        split_kernel<<<(unsigned)((n4 + 255) / 256), 256>>>(x, x_hi, x_lo, n4);
        n4 = (size_t)D_HID * D_IN / 4;
        split_kernel<<<(unsigned)((n4 + 255) / 256), 256>>>(W_hx, whx_hi, whx_lo, n4);
        n4 = (size_t)N_CLS * D_HID / 4;
        split_kernel<<<(unsigned)((n4 + 255) / 256), 256>>>(W_ph, wph_hi, wph_lo, n4);
        transpose_split<<<dim3(D_HID / 32, D_HID / 32), dim3(32, 8)>>>(
            W_hh, whh_hi, whh_lo, whh_hiT, whh_loT);
    }

    // 1) xproj = x @ W_hx^T + b_h -> fp32 + hi/lo   (M=32768, N=2048, K=1024)
    {
        dim3 grid(D_HID / 128, (BATCH * SEQ) / 256);
        kXproj<<<grid, 512, SMEM_BIG>>>(
            BATCH * SEQ, D_HID, D_IN,
            x_hi, x_lo, (size_t)D_IN, (size_t)256 * D_IN,
            whx_hi, whx_lo,
            nullptr, 0, 0, b_h,
            xproj, xp_hi, xp_lo);
    }

    // 2) log-depth scan: 7 combine levels + 6 squarings
    const bf *pBh = whh_hi, *pBl = whh_lo, *pTh = whh_hiT, *pTl = whh_loT;
    const bf *Ah = xp_hi, *Al = xp_lo;
    const float* AddB = xproj + D_HID;
    size_t ldA = (size_t)SEQ * D_HID, bsA = (size_t)2 * D_HID;
    size_t ldAd = (size_t)SEQ * D_HID, bsAd = (size_t)2 * D_HID;
    int ps = 0;
    for (int lvl = 1; lvl <= 7; lvl++) {
        const int nout = 128 >> lvl;
        const int Ml   = nout * BATCH;
        float* of = (lvl & 1) ? dA_f : dB_f;
        bf*    oh = (lvl & 1) ? dA_h : dB_h;
        bf*    ol = (lvl & 1) ? dA_l : dB_l;
        {
            dim3 grid(D_HID / 128, Ml / 256);
            kComb<<<grid, 512, SMEM_BIG>>>(
                Ml, D_HID, D_HID, Ah, Al, ldA, bsA, pBh, pBl,
                AddB, ldAd, bsAd, nullptr, of, oh, ol);
        }
        if (lvl < 7) {
            dim3 grid(D_HID / 128, D_HID / 256);
            kSquare<<<grid, 512, SMEM_BIG>>>(
                D_HID, D_HID, D_HID,
                pBh, pBl, (size_t)D_HID, (size_t)256 * D_HID,
                pTh, pTl,
                nullptr, 0, 0, nullptr, pw_f32, nullptr, nullptr);
            transpose_split<<<dim3(D_HID / 32, D_HID / 32), dim3(32, 8)>>>(
                pw_f32, pw_hi + ps * PW, pw_lo + ps * PW,
                pw_hiT + ps * PW, pw_loT + ps * PW);
            pBh = pw_hi + ps * PW; pBl = pw_lo + ps * PW;
            pTh = pw_hiT + ps * PW; pTl = pw_loT + ps * PW;
            ps ^= 1;
        }
        Ah = oh; Al = ol;
        AddB = of + (size_t)BATCH * D_HID;
        ldA = D_HID;  bsA = (size_t)2 * BATCH * D_HID;
        ldAd = D_HID; bsAd = (size_t)2 * BATCH * D_HID;
    }

    // 3) readout: out = h_T @ W_ph^T + b_p   (M=256, N=1024, K=2048)
    {
        dim3 grid(N_CLS / 64, BATCH / 64);
        kOut<<<grid, 128, SMEM_SM>>>(
            BATCH, N_CLS, D_HID,
            Ah, Al, (size_t)D_HID, (size_t)256 * D_HID,
            wph_hi, wph_lo,
            nullptr, 0, 0, b_p, out, nullptr, nullptr);
    }
}

// round 16
// speedup vs baseline: 1.4643x; 1.4643x over previous
#include <cuda_runtime.h>
#include <cuda_bf16.h>
#include <cstdint>

#define BATCH 256
#define SEQ   128
#define D_IN  1024
#define D_HID 2048
#define N_CLS 1024

typedef __nv_bfloat16 bf;

// ---------------- scratch (__device__ globals; no cudaMalloc allowed) -------
__device__ bf    g_x_hi [(size_t)BATCH * SEQ * D_IN];              // 67 MB
__device__ bf    g_x_lo [(size_t)BATCH * SEQ * D_IN];
__device__ bf    g_Wph_hi[(size_t)N_CLS * D_HID];
__device__ bf    g_Wph_lo[(size_t)N_CLS * D_HID];
__device__ bf    g_whh_hi [(size_t)D_HID * D_HID];
__device__ bf    g_whh_lo [(size_t)D_HID * D_HID];
__device__ bf    g_whh_hiT[(size_t)D_HID * D_HID];
__device__ bf    g_whh_loT[(size_t)D_HID * D_HID];
__device__ bf    g_pw_hi [2][(size_t)D_HID * D_HID];
__device__ bf    g_pw_lo [2][(size_t)D_HID * D_HID];
__device__ bf    g_pw_hiT[2][(size_t)D_HID * D_HID];
__device__ bf    g_pw_loT[2][(size_t)D_HID * D_HID];
__device__ float g_pw_f32[(size_t)D_HID * D_HID];
// folded weights: Bcat[n, i*1024+c] = (W^{7-i} W_hx)[n, c]
__device__ bf    g_Bcat_hi[(size_t)D_HID * 8 * D_IN];              // 33.5 MB
__device__ bf    g_Bcat_lo[(size_t)D_HID * 8 * D_IN];
// chain state Gt_j = (W^j W_hx)^T : [1024, 2048]
__device__ bf    g_gt_hi[2][(size_t)D_IN * D_HID];
__device__ bf    g_gt_lo[2][(size_t)D_IN * D_HID];
__device__ float g_bb[2][D_HID];                                    // bias chain
// scan buffers: 16 seqs of [256, 2048]
__device__ float g_dA_f[(size_t)16 * BATCH * D_HID];
__device__ bf    g_dA_h[(size_t)16 * BATCH * D_HID];
__device__ bf    g_dA_l[(size_t)16 * BATCH * D_HID];
__device__ float g_dB_f[(size_t)8 * BATCH * D_HID];
__device__ bf    g_dB_h[(size_t)8 * BATCH * D_HID];
__device__ bf    g_dB_l[(size_t)8 * BATCH * D_HID];

// ---------------- portable PTX helpers (compute_103 baseline, no 'a') -------
__device__ __forceinline__ uint32_t smem_to_u32(const void* p) {
    uint32_t a;
    asm("{ .reg .u64 t; cvta.to.shared.u64 t, %1; cvt.u32.u64 %0, t; }" : "=r"(a) : "l"(p));
    return a;
}
#define CP_ASYNC16(dst, src) \
    asm volatile("cp.async.cg.shared.global [%0], [%1], 16;" :: "r"(dst), "l"(src) : "memory")
#define CP_COMMIT() asm volatile("cp.async.commit_group;" ::: "memory")
#define CP_WAIT0()  asm volatile("cp.async.wait_group 0;" ::: "memory")
#define CP_WAIT1()  asm volatile("cp.async.wait_group 1;" ::: "memory")

__device__ __forceinline__ void ldsm_x4(uint32_t* r, uint32_t addr) {
    asm volatile("ldmatrix.sync.aligned.m8n8.x4.shared.b16 {%0,%1,%2,%3}, [%4];"
                 : "=r"(r[0]), "=r"(r[1]), "=r"(r[2]), "=r"(r[3]) : "r"(addr));
}
__device__ __forceinline__ void mma_bf16(float* c, const uint32_t* a, const uint32_t* b) {
    asm volatile("mma.sync.aligned.m16n8k16.row.col.f32.bf16.bf16.f32 "
                 "{%0,%1,%2,%3}, {%4,%5,%6,%7}, {%8,%9}, {%0,%1,%2,%3};"
                 : "+f"(c[0]), "+f"(c[1]), "+f"(c[2]), "+f"(c[3])
                 : "r"(a[0]), "r"(a[1]), "r"(a[2]), "r"(a[3]), "r"(b[0]), "r"(b[1]));
}
__device__ __forceinline__ uint32_t swz(uint32_t off) {
    return off ^ ((off >> 3) & 0x70);
}
__device__ __forceinline__ void split1(float v, bf& h, bf& l) {
    h = __float2bfloat16(v);
    l = __float2bfloat16(v - __bfloat162float(h));
}

// ---------------------------------------------------------------------------
// HMMA split-bf16 GEMM (3 products: Ahi.Bhi + Ahi.Blo + Alo.Bhi), fp32 accum.
// A row m -> A + (m/256)*bsA + (m%256)*ldA.  B: [N,K] row-major, ldB == K.
// PARITY: seq = 256 rows; even seq -> hi/lo only; odd seq -> fp32 only.
// ---------------------------------------------------------------------------
template <int BM, int BN, int WM, int WN, bool ADD, bool BIAS, bool OUT_F32,
          bool OUT_SPLIT, bool PARITY>
__global__ __launch_bounds__((BM / WM) * (BN / WN) * 32) void rnn_gemm(
    int M, int N, int K,
    const bf* __restrict__ Ahi, const bf* __restrict__ Alo, size_t ldA, size_t bsA,
    const bf* __restrict__ Bhi, const bf* __restrict__ Blo,
    const float* __restrict__ Add, size_t ldAdd, size_t bsAdd,
    const float* __restrict__ bias,
    float* __restrict__ C, bf* __restrict__ Chi, bf* __restrict__ Clo)
{
    constexpr int THREADS = (BM / WM) * (BN / WN) * 32;
    constexpr int ATILE = BM * 128;
    constexpr int BTILE = BN * 128;
    constexpr int BUF = 2 * ATILE + 2 * BTILE;
    constexpr int MI = WM / 16, NI = WN / 8, NJ = WN / 16;

    extern __shared__ __align__(1024) char smem[];
    const uint32_t sbase = smem_to_u32(smem);

    const int tid  = threadIdx.x;
    const int lane = tid & 31;
    const int wid  = tid >> 5;
    constexpr int WARPS_N = BN / WN;
    const int warp_n = wid % WARPS_N;
    const int warp_m = wid / WARPS_N;
    const int bn = blockIdx.x;
    const int bm = blockIdx.y;

    const size_t blk   = (size_t)((unsigned)(bm * BM) >> 8);
    const int    rowin = (bm * BM) & 255;
    const bf* AhE = Ahi + blk * bsA + (size_t)rowin * ldA;
    const bf* AlE = Alo + blk * bsA + (size_t)rowin * ldA;
    const float* AddE = nullptr;
    if (ADD) AddE = Add + blk * bsAdd + (size_t)rowin * ldAdd;
    const int par = PARITY ? ((int)blk & 1) : 0;

    const int NIT = K >> 6;

    auto issueTiles = [&](int it, int buf) {
        const int kb = it << 6;
        const char* AgH = (const char*)(AhE + kb);
        const char* AgL = (const char*)(AlE + kb);
        const char* BgH = (const char*)(Bhi + (size_t)(bn * BN) * K + kb);
        const char* BgL = (const char*)(Blo + (size_t)(bn * BN) * K + kb);
        const uint32_t s0 = sbase + buf * BUF;
        const size_t rsA = ldA * 2;
        const size_t rsB = (size_t)K * 2;
#pragma unroll
        for (int j = 0; j < BM * 8 / THREADS; j++) {
            int c = tid + j * THREADS;
            int r = c >> 3, col = (c & 7) << 4;
            uint32_t off = swz((uint32_t)(r * 128 + col));
            size_t g = (size_t)r * rsA + col;
            CP_ASYNC16(s0 + off, AgH + g);
            CP_ASYNC16(s0 + ATILE + off, AgL + g);
        }
#pragma unroll
        for (int j = 0; j < BN * 8 / THREADS; j++) {
            int c = tid + j * THREADS;
            int r = c >> 3, col = (c & 7) << 4;
            uint32_t off = swz((uint32_t)(r * 128 + col));
            size_t g = (size_t)r * rsB + col;
            CP_ASYNC16(s0 + 2 * ATILE + off, BgH + g);
            CP_ASYNC16(s0 + 2 * ATILE + BTILE + off, BgL + g);
        }
    };

    float acc[MI][NI][4];
#pragma unroll
    for (int i = 0; i < MI; i++)
#pragma unroll
        for (int j = 0; j < NI; j++)
#pragma unroll
            for (int e = 0; e < 4; e++) acc[i][j][e] = 0.0f;

    issueTiles(0, 0);
    CP_COMMIT();

    for (int it = 0; it < NIT; it++) {
        const int buf = it & 1;
        if (it + 1 < NIT) {
            issueTiles(it + 1, buf ^ 1);
            CP_COMMIT();
            CP_WAIT1();
        } else {
            CP_WAIT0();
        }
        __syncthreads();

        const uint32_t sAh = sbase + buf * BUF;
        const uint32_t sAl = sAh + ATILE;
        const uint32_t sBh = sAh + 2 * ATILE;
        const uint32_t sBl = sBh + BTILE;
#pragma unroll
        for (int s = 0; s < 4; s++) {
            const int k0 = s * 16;
            uint32_t ah[MI][4], al[MI][4], bh[NJ][4], bl[NJ][4];
#pragma unroll
            for (int i = 0; i < MI; i++) {
                int row = warp_m * WM + i * 16 + (lane & 15);
                int kc  = k0 + (lane >> 4) * 8;
                uint32_t off = swz((uint32_t)(row * 128 + kc * 2));
                ldsm_x4(ah[i], sAh + off);
                ldsm_x4(al[i], sAl + off);
            }
#pragma unroll
            for (int j = 0; j < NJ; j++) {
                int n  = warp_n * WN + j * 16 + (lane & 7) + ((lane >> 4) & 1) * 8;
                int kc = k0 + ((lane >> 3) & 1) * 8;
                uint32_t off = swz((uint32_t)(n * 128 + kc * 2));
                ldsm_x4(bh[j], sBh + off);
                ldsm_x4(bl[j], sBl + off);
            }
#pragma unroll
            for (int i = 0; i < MI; i++)
#pragma unroll
                for (int j = 0; j < NI; j++) {
                    mma_bf16(acc[i][j], ah[i], &bh[j >> 1][(j & 1) * 2]);
                    mma_bf16(acc[i][j], ah[i], &bl[j >> 1][(j & 1) * 2]);
                    mma_bf16(acc[i][j], al[i], &bh[j >> 1][(j & 1) * 2]);
                }
        }
        __syncthreads();
    }

    // ---- epilogue ----
    const int tg = lane >> 2, tr = lane & 3;
#pragma unroll
    for (int i = 0; i < MI; i++) {
#pragma unroll
        for (int j = 0; j < NI; j++) {
            const int col = bn * BN + warp_n * WN + j * 8 + tr * 2;
            const int lr0 = warp_m * WM + i * 16 + tg;
            const int lr1 = lr0 + 8;
            const int row0 = bm * BM + lr0;
            const int row1 = bm * BM + lr1;
            float2 v0 = make_float2(acc[i][j][0], acc[i][j][1]);
            float2 v1 = make_float2(acc[i][j][2], acc[i][j][3]);
            if (ADD) {
                float2 a0 = *(const float2*)&AddE[(size_t)lr0 * ldAdd + col];
                float2 a1 = *(const float2*)&AddE[(size_t)lr1 * ldAdd + col];
                v0.x += a0.x; v0.y += a0.y; v1.x += a1.x; v1.y += a1.y;
            }
            if (BIAS) {
                float2 bb = *(const float2*)&bias[col];
                v0.x += bb.x; v0.y += bb.y; v1.x += bb.x; v1.y += bb.y;
            }
            if (OUT_F32 && (!PARITY || par == 1)) {
                *(float2*)&C[(size_t)row0 * N + col] = v0;
                *(float2*)&C[(size_t)row1 * N + col] = v1;
            }
            if (OUT_SPLIT && (!PARITY || par == 0)) {
                bf h0, h1, h2, h3, l0, l1, l2, l3;
                split1(v0.x, h0, l0); split1(v0.y, h1, l1);
                split1(v1.x, h2, l2); split1(v1.y, h3, l3);
                __nv_bfloat162 hp0{h0, h1}, hp1{h2, h3}, lp0{l0, l1}, lp1{l2, l3};
                *(uint32_t*)&Chi[(size_t)row0 * N + col] = *(uint32_t*)&hp0;
                *(uint32_t*)&Chi[(size_t)row1 * N + col] = *(uint32_t*)&hp1;
                *(uint32_t*)&Clo[(size_t)row0 * N + col] = *(uint32_t*)&lp0;
                *(uint32_t*)&Clo[(size_t)row1 * N + col] = *(uint32_t*)&lp1;
            }
        }
    }
}

// ---------------- fp32 -> bf16 hi/lo split (plain contiguous) ----------------
__global__ void split_kernel(const float* __restrict__ src,
                             bf* __restrict__ hi, bf* __restrict__ lo, size_t n4)
{
    size_t i = (size_t)blockIdx.x * blockDim.x + threadIdx.x;
    if (i >= n4) return;
    float4 v = ((const float4*)src)[i];
    bf h0, h1, h2, h3, l0, l1, l2, l3;
    split1(v.x, h0, l0); split1(v.y, h1, l1); split1(v.z, h2, l2); split1(v.w, h3, l3);
    __nv_bfloat162 hp0{h0, h1}, hp1{h2, h3}, lp0{l0, l1}, lp1{l2, l3};
    uint2 hw, lw;
    hw.x = *(uint32_t*)&hp0; hw.y = *(uint32_t*)&hp1;
    lw.x = *(uint32_t*)&lp0; lw.y = *(uint32_t*)&lp1;
    ((uint2*)hi)[i] = hw;
    ((uint2*)lo)[i] = lw;
}

// ------- generalized transpose+split: src fp32 [R,C] (ld=C) -----------------
// plain hi/lo -> [R, ldP] at pHi/pLo; transposed hi/lo -> [C, ldT] at tHi/tLo.
__global__ void tsg(const float* __restrict__ src, int C,
                    bf* __restrict__ pHi, bf* __restrict__ pLo, int ldP,
                    bf* __restrict__ tHi, bf* __restrict__ tLo, int ldT)
{
    __shared__ float t[32][33];
    const int bx = blockIdx.x * 32;  // col
    const int by = blockIdx.y * 32;  // row
    const int tx = threadIdx.x, ty = threadIdx.y;  // 32 x 8
#pragma unroll
    for (int j = 0; j < 4; j++) {
        int r = by + ty + j * 8;
        float v = src[(size_t)r * C + bx + tx];
        t[ty + j * 8][tx] = v;
        if (pHi) {
            bf h, l; split1(v, h, l);
            pHi[(size_t)r * ldP + bx + tx] = h;
            pLo[(size_t)r * ldP + bx + tx] = l;
        }
    }
    __syncthreads();
    if (tHi) {
#pragma unroll
        for (int j = 0; j < 4; j++) {
            int ct = ty + j * 8;
            float v = t[tx][ct];                    // = src[by+tx][bx+ct]
            bf h, l; split1(v, h, l);
            tHi[(size_t)(bx + ct) * ldT + by + tx] = h;
            tLo[(size_t)(bx + ct) * ldT + by + tx] = l;
        }
    }
}

// ---------------- fp32 GEMV: y = W x + b  (W [2048,2048]) --------------------
__global__ void gemv_wxb(const float* __restrict__ W, const float* __restrict__ x,
                         const float* __restrict__ b, float* __restrict__ y)
{
    const int wid = threadIdx.x >> 5, lane = threadIdx.x & 31;
    const int r = blockIdx.x * 8 + wid;
    const float* row = W + (size_t)r * D_HID;
    float s = 0.0f;
    for (int k = lane; k < D_HID; k += 32) s += row[k] * x[k];
#pragma unroll
    for (int o = 16; o; o >>= 1) s += __shfl_xor_sync(0xFFFFFFFFu, s, o);
    if (lane == 0) y[r] = s + b[r];
}

// ---------------------------------------------------------------------------
extern "C" void kernel_launch(void* const* d_in, const int* in_sizes, int n_in,
                              void* d_out, int out_size)
{
    const float* x    = (const float*)d_in[0];
    const float* W_hx = (const float*)d_in[1];
    const float* W_hh = (const float*)d_in[2];
    const float* W_ph = (const float*)d_in[3];
    const float* b_h  = (const float*)d_in[4];
    const float* b_p  = (const float*)d_in[5];
    float* out = (float*)d_out;

    bf *x_hi, *x_lo, *wph_hi, *wph_lo;
    bf *whh_hi, *whh_lo, *whh_hiT, *whh_loT;
    bf *pw_hi, *pw_lo, *pw_hiT, *pw_loT;
    bf *Bcat_hi, *Bcat_lo, *gt_hi, *gt_lo;
    bf *dA_h, *dA_l, *dB_h, *dB_l;
    float *pw_f32, *bbv, *dA_f, *dB_f;
    cudaGetSymbolAddress((void**)&x_hi,    g_x_hi);
    cudaGetSymbolAddress((void**)&x_lo,    g_x_lo);
    cudaGetSymbolAddress((void**)&wph_hi,  g_Wph_hi);
    cudaGetSymbolAddress((void**)&wph_lo,  g_Wph_lo);
    cudaGetSymbolAddress((void**)&whh_hi,  g_whh_hi);
    cudaGetSymbolAddress((void**)&whh_lo,  g_whh_lo);
    cudaGetSymbolAddress((void**)&whh_hiT, g_whh_hiT);
    cudaGetSymbolAddress((void**)&whh_loT, g_whh_loT);
    cudaGetSymbolAddress((void**)&pw_hi,   g_pw_hi);
    cudaGetSymbolAddress((void**)&pw_lo,   g_pw_lo);
    cudaGetSymbolAddress((void**)&pw_hiT,  g_pw_hiT);
    cudaGetSymbolAddress((void**)&pw_loT,  g_pw_loT);
    cudaGetSymbolAddress((void**)&pw_f32,  g_pw_f32);
    cudaGetSymbolAddress((void**)&Bcat_hi, g_Bcat_hi);
    cudaGetSymbolAddress((void**)&Bcat_lo, g_Bcat_lo);
    cudaGetSymbolAddress((void**)&gt_hi,   g_gt_hi);
    cudaGetSymbolAddress((void**)&gt_lo,   g_gt_lo);
    cudaGetSymbolAddress((void**)&bbv,     g_bb);
    cudaGetSymbolAddress((void**)&dA_f,    g_dA_f);
    cudaGetSymbolAddress((void**)&dA_h,    g_dA_h);
    cudaGetSymbolAddress((void**)&dA_l,    g_dA_l);
    cudaGetSymbolAddress((void**)&dB_f,    g_dB_f);
    cudaGetSymbolAddress((void**)&dB_h,    g_dB_h);
    cudaGetSymbolAddress((void**)&dB_l,    g_dB_l);
    const size_t PW = (size_t)D_HID * D_HID;
    const size_t GT = (size_t)D_IN * D_HID;

    auto kFx   = rnn_gemm<128, 128, 64, 32, false, true,  true,  true,  true>;
    auto kComb = rnn_gemm<128, 128, 64, 32, true,  false, true,  true,  true>;
    auto kSq   = rnn_gemm<128, 128, 64, 32, false, false, true,  false, false>;
    auto kOut  = rnn_gemm<64,  64,  32, 32, false, true,  true,  false, false>;
    const int SMEM_BIG = 2 * (2 * 128 * 128 + 2 * 128 * 128);   // 131072
    const int SMEM_SM  = 2 * (2 * 64 * 128 + 2 * 64 * 128);     // 65536
    cudaFuncSetAttribute(kFx,   cudaFuncAttributeMaxDynamicSharedMemorySize, SMEM_BIG);
    cudaFuncSetAttribute(kComb, cudaFuncAttributeMaxDynamicSharedMemorySize, SMEM_BIG);
    cudaFuncSetAttribute(kSq,   cudaFuncAttributeMaxDynamicSharedMemorySize, SMEM_BIG);
    cudaFuncSetAttribute(kOut,  cudaFuncAttributeMaxDynamicSharedMemorySize, SMEM_SM);

    // 0) splits of x, W_ph; W_hh both orientations; W_hx -> Bcat slot 7 + Gt_0
    {
        size_t n4 = (size_t)BATCH * SEQ * D_IN / 4;
        split_kernel<<<(unsigned)((n4 + 255) / 256), 256>>>(x, x_hi, x_lo, n4);
        n4 = (size_t)N_CLS * D_HID / 4;
        split_kernel<<<(unsigned)((n4 + 255) / 256), 256>>>(W_ph, wph_hi, wph_lo, n4);
        tsg<<<dim3(D_HID / 32, D_HID / 32), dim3(32, 8)>>>(
            W_hh, D_HID, whh_hi, whh_lo, D_HID, whh_hiT, whh_loT, D_HID);
        tsg<<<dim3(D_IN / 32, D_HID / 32), dim3(32, 8)>>>(
            W_hx, D_IN, Bcat_hi + 7 * D_IN, Bcat_lo + 7 * D_IN, 8 * D_IN,
            gt_hi, gt_lo, D_HID);
    }

    // 1) bias chain: bb8 = sum_{i=0..7} W^i b  via s_{k+1} = W s_k + b (fp32)
    const float* bcur = b_h;
    for (int k = 0; k < 7; k++) {
        float* o = bbv + (k & 1) * D_HID;
        gemv_wxb<<<D_HID / 8, 256>>>(W_hh, bcur, b_h, o);
        bcur = o;
    }

    // 2) weight chain: Gt_j = Gt_{j-1} * W^T-form GEMM; G_j -> Bcat slot 7-j
    for (int j = 1; j <= 7; j++) {
        int pj = (j - 1) & 1, cj = j & 1;
        dim3 grid(D_HID / 128, D_IN / 128);
        kSq<<<grid, 256, SMEM_BIG>>>(
            D_IN, D_HID, D_HID,
            gt_hi + pj * GT, gt_lo + pj * GT, (size_t)D_HID, (size_t)256 * D_HID,
            whh_hi, whh_lo,
            nullptr, 0, 0, nullptr, pw_f32, nullptr, nullptr);
        tsg<<<dim3(D_HID / 32, D_IN / 32), dim3(32, 8)>>>(
            pw_f32, D_HID,
            gt_hi + cj * GT, gt_lo + cj * GT, D_HID,
            Bcat_hi + (7 - j) * D_IN, Bcat_lo + (7 - j) * D_IN, 8 * D_IN);
    }

    // 3) fused xproj+levels1-3: d[j*256+b, :] = Bcat . x[b, 8j:8j+8, :] + bb8
    //    M=4096, N=2048, K=8192; A row m: blk=j (bsA=8*D_IN), rowin=b (ldA=SEQ*D_IN)
    {
        dim3 grid(D_HID / 128, (16 * BATCH) / 128);
        kFx<<<grid, 256, SMEM_BIG>>>(
            16 * BATCH, D_HID, 8 * D_IN,
            x_hi, x_lo, (size_t)SEQ * D_IN, (size_t)8 * D_IN,
            Bcat_hi, Bcat_lo,
            nullptr, 0, 0, bcur,
            dA_f, dA_h, dA_l);
    }

    // 4) powers + 4 combine levels (16 -> 8 -> 4 -> 2 -> 1)
    //    squaring chain: W2(s0), W4(s1), W8(s0), W16(s1), W32(s0), W64(s1)
    auto square = [&](const bf* ph, const bf* pl, const bf* th, const bf* tl, int slot) {
        dim3 grid(D_HID / 128, D_HID / 128);
        kSq<<<grid, 256, SMEM_BIG>>>(
            D_HID, D_HID, D_HID,
            ph, pl, (size_t)D_HID, (size_t)256 * D_HID, th, tl,
            nullptr, 0, 0, nullptr, pw_f32, nullptr, nullptr);
        tsg<<<dim3(D_HID / 32, D_HID / 32), dim3(32, 8)>>>(
            pw_f32, D_HID,
            pw_hi + slot * PW, pw_lo + slot * PW, D_HID,
            pw_hiT + slot * PW, pw_loT + slot * PW, D_HID);
    };
    square(whh_hi, whh_lo, whh_hiT, whh_loT, 0);                      // W2 -> s0
    square(pw_hi, pw_lo, pw_hiT, pw_loT, 1);                          // W4 -> s1
    square(pw_hi + PW, pw_lo + PW, pw_hiT + PW, pw_loT + PW, 0);      // W8 -> s0

    const float* Af = dA_f; const bf *Ah = dA_h, *Al = dA_l;
    float* Bf = dB_f; bf *Bh = dB_h, *Bl = dB_l;
    int pslot = 0;   // slot holding the power for the next combine
    for (int lv = 0; lv < 4; lv++) {
        const int nout = 8 >> lv;                 // 8,4,2,1
        const int Ml = nout * BATCH;
        dim3 grid(D_HID / 128, Ml / 128);
        kComb<<<grid, 256, SMEM_BIG>>>(
            Ml, D_HID, D_HID,
            Ah, Al, (size_t)D_HID, (size_t)2 * BATCH * D_HID,
            pw_hi + pslot * PW, pw_lo + pslot * PW,
            Af + (size_t)BATCH * D_HID, (size_t)D_HID, (size_t)2 * BATCH * D_HID,
            nullptr, Bf, Bh, Bl);
        if (lv < 3) {
            square(pw_hi + pslot * PW, pw_lo + pslot * PW,
                   pw_hiT + pslot * PW, pw_loT + pslot * PW, pslot ^ 1);
            pslot ^= 1;
        }
        // swap A/B roles
        const float* tf = Af; const bf *th = Ah, *tl = Al;
        Af = Bf; Ah = Bh; Al = Bl;
        Bf = (float*)tf; Bh = (bf*)th; Bl = (bf*)tl;
    }

    // 5) readout: out = h @ W_ph^T + b_p   (M=256, N=1024, K=2048)
    {
        dim3 grid(N_CLS / 64, BATCH / 64);
        kOut<<<grid, 128, SMEM_SM>>>(
            BATCH, N_CLS, D_HID,
            Ah, Al, (size_t)D_HID, (size_t)256 * D_HID,
            wph_hi, wph_lo,
            nullptr, 0, 0, b_p, out, nullptr, nullptr);
    }
}